// round 1
// baseline (speedup 1.0000x reference)
#include <cuda_runtime.h>
#include <cstdint>

// Output: [B=16, T=50, H=100, W=100, P=25] fp32 = 200M elems = 800MB.
// Strategy: HBM-write-bound memset (STG.128) + 20k-element scatter of 1.0f.

static constexpr int B = 16;
static constexpr int T = 50;
static constexpr int H = 100;
static constexpr int W = 100;
static constexpr int P = 25;

// ---------------------------------------------------------------------------
// Kernel 1: zero the output with 128-bit stores.
// ---------------------------------------------------------------------------
__global__ void zero_kernel(float4* __restrict__ out, long long n_vec4) {
    long long i = (long long)blockIdx.x * blockDim.x + threadIdx.x;
    if (i < n_vec4) {
        out[i] = make_float4(0.f, 0.f, 0.f, 0.f);
    }
}

__global__ void zero_tail_kernel(float* __restrict__ out, long long start, long long n) {
    long long i = start + (long long)blockIdx.x * blockDim.x + threadIdx.x;
    if (i < n) out[i] = 0.f;
}

// ---------------------------------------------------------------------------
// Kernel 2: scatter 1.0f at (b, t, row, col, p).
//   points  = x.reshape(B,T,P,2); col = pt[...,0], row = pt[...,1]
//   idx = (int)(pt / resolution + origin)   (trunc toward zero; inputs positive)
// ---------------------------------------------------------------------------
__global__ void scatter_kernel(const float* __restrict__ x,
                               const float* __restrict__ resolution,
                               const float* __restrict__ origin,
                               float* __restrict__ out) {
    int gid = blockIdx.x * blockDim.x + threadIdx.x;   // over B*T*P = 20000
    if (gid >= B * T * P) return;

    int p  = gid % P;
    int bt = gid / P;          // b*T + t

    const float px = x[bt * (2 * P) + 2 * p + 0];      // x-coordinate -> col
    const float py = x[bt * (2 * P) + 2 * p + 1];      // y-coordinate -> row

    const float rx = resolution[bt * 2 + 0];
    const float ry = resolution[bt * 2 + 1];
    const float ox = origin[bt * 2 + 0];
    const float oy = origin[bt * 2 + 1];

    int col = (int)(px / rx + ox);
    int row = (int)(py / ry + oy);

    // JAX .at[].set drops out-of-bounds scatter updates; mirror that.
    if (row < 0 || row >= H || col < 0 || col >= W) return;

    long long off = ((((long long)bt) * H + row) * W + col) * P + p;
    out[off] = 1.0f;
}

// ---------------------------------------------------------------------------
extern "C" void kernel_launch(void* const* d_in, const int* in_sizes, int n_in,
                              void* d_out, int out_size) {
    const float* x          = (const float*)d_in[0];
    const float* resolution = (const float*)d_in[1];
    const float* origin     = (const float*)d_in[2];
    float* out = (float*)d_out;

    const long long n = (long long)out_size;           // 200,000,000
    const long long n_vec4 = n / 4;
    const long long tail = n - n_vec4 * 4;

    {
        const int threads = 256;
        const long long blocks = (n_vec4 + threads - 1) / threads;
        zero_kernel<<<(unsigned)blocks, threads>>>((float4*)out, n_vec4);
        if (tail > 0) {
            zero_tail_kernel<<<1, 32>>>(out, n_vec4 * 4, n);
        }
    }

    {
        const int total = B * T * P;                   // 20,000
        const int threads = 256;
        const int blocks = (total + threads - 1) / threads;
        scatter_kernel<<<blocks, threads>>>(x, resolution, origin, out);
    }
}